// round 1
// baseline (speedup 1.0000x reference)
#include <cuda_runtime.h>
#include <math_constants.h>

#define N_PTS 500
#define K12 12
#define KPP 4

// ---------------- scratch (device globals; no allocation) ----------------
__device__ float g_cf[128 * N_PTS];        // pfeat(cloud_tar)
__device__ float g_ctf[128 * N_PTS];       // pfeat(cloud)
__device__ float g_iff_cur[128 * N_PTS];   // ifeat(img_tar)
__device__ float g_iff_tar[128 * N_PTS];   // ifeat(img)
__device__ int   g_inds[N_PTS * K12];      // knn(ref=cloud, query=cloud_tar, 12)
__device__ int   g_inds_self[N_PTS * K12]; // knn(ct, ct, 12)
__device__ int   g_inds_pp[N_PTS * KPP];   // knn(ref=ct, query=cloud, 4)
__device__ float g_wct[N_PTS * K12];       // exp(-d) numerators
__device__ float g_wcc[N_PTS * K12];
__device__ float g_sum[2];                 // softmax denominators
__device__ float g_A[256 * N_PTS];         // [img_diff ; spd]
__device__ float g_B[256 * N_PTS];         // [cloud_diff ; sid]
__device__ float g_C[128 * N_PTS];         // [fuse_p ; fuse_i]
__device__ float g_F[160 * N_PTS];         // fuse_t_c
__device__ float g_X1[256 * N_PTS];
__device__ float g_X2[1024 * N_PTS];
__device__ float g_X3[160 * N_PTS];

__device__ __forceinline__ float* buf_ptr(int id) {
    switch (id) {
        case 0: return g_A;
        case 1: return g_B;
        case 2: return g_C;
        case 3: return g_F;
        case 4: return g_X1;
        case 5: return g_X2;
        case 6: return g_X3;
        case 7: return g_C + 64 * N_PTS;
    }
    return nullptr;
}

// ---------------- KNN: one thread per query, register insertion sort ------
// Matches jax.lax.top_k(-d2, k) tie rules: strict '<' acceptance + strict '<' bubble
// keeps the lower index first for equal distances.
template <int K>
__global__ void knn_kernel(const float* __restrict__ ref,
                           const float* __restrict__ query,
                           int task) {
    __shared__ float rx[N_PTS], ry[N_PTS], rz[N_PTS], rr[N_PTS];
    for (int i = threadIdx.x; i < N_PTS; i += blockDim.x) {
        float x = ref[i * 3 + 0], y = ref[i * 3 + 1], z = ref[i * 3 + 2];
        rx[i] = x; ry[i] = y; rz[i] = z;
        rr[i] = x * x + y * y + z * z;
    }
    __syncthreads();
    int q = blockIdx.x * blockDim.x + threadIdx.x;
    if (q >= N_PTS) return;
    float qx = query[q * 3 + 0], qy = query[q * 3 + 1], qz = query[q * 3 + 2];
    float qq = qx * qx + qy * qy + qz * qz;

    float dist[K];
    int idx[K];
#pragma unroll
    for (int t = 0; t < K; t++) { dist[t] = CUDART_INF_F; idx[t] = 0; }

    for (int r = 0; r < N_PTS; r++) {
        float dot = qx * rx[r] + qy * ry[r] + qz * rz[r];
        float d2 = qq - 2.0f * dot + rr[r];
        if (d2 < dist[K - 1]) {
            dist[K - 1] = d2; idx[K - 1] = r;
#pragma unroll
            for (int t = K - 1; t > 0; --t) {
                if (dist[t] < dist[t - 1]) {
                    float td = dist[t]; dist[t] = dist[t - 1]; dist[t - 1] = td;
                    int ti = idx[t]; idx[t] = idx[t - 1]; idx[t - 1] = ti;
                }
            }
        }
    }
    int* out = (task == 0) ? g_inds : (task == 1) ? g_inds_self : g_inds_pp;
#pragma unroll
    for (int t = 0; t < K; t++) out[q * K + t] = idx[t];
}

// ---------------- fused 2-layer 1x1 conv features (4 tasks) ---------------
// y=0: g_cf   = pconv2(lrelu(pconv1(cloud_tar)))
// y=1: g_ctf  = pconv2(lrelu(pconv1(cloud)))
// y=2: g_iff_cur = conv2(lrelu(conv1(img_tar)))
// y=3: g_iff_tar = conv2(lrelu(conv1(img)))
__global__ void feat_kernel(const float* __restrict__ img,
                            const float* __restrict__ img_tar,
                            const float* __restrict__ cloud,
                            const float* __restrict__ cloud_tar,
                            const float* __restrict__ Wc1, const float* __restrict__ bc1,
                            const float* __restrict__ Wc2, const float* __restrict__ bc2,
                            const float* __restrict__ Wp1, const float* __restrict__ bp1,
                            const float* __restrict__ Wp2, const float* __restrict__ bp2) {
    int task = blockIdx.y;
    int n = blockIdx.x;
    __shared__ float xin[32];
    __shared__ float hid[64];
    const float *W1, *b1, *W2, *b2;
    float* out;
    int in_ch;
    if (task == 0) {
        in_ch = 3; W1 = Wp1; b1 = bp1; W2 = Wp2; b2 = bp2; out = g_cf;
        if (threadIdx.x < 3) xin[threadIdx.x] = cloud_tar[n * 3 + threadIdx.x];
    } else if (task == 1) {
        in_ch = 3; W1 = Wp1; b1 = bp1; W2 = Wp2; b2 = bp2; out = g_ctf;
        if (threadIdx.x < 3) xin[threadIdx.x] = cloud[n * 3 + threadIdx.x];
    } else if (task == 2) {
        in_ch = 32; W1 = Wc1; b1 = bc1; W2 = Wc2; b2 = bc2; out = g_iff_cur;
        if (threadIdx.x < 32) xin[threadIdx.x] = img_tar[threadIdx.x * N_PTS + n];
    } else {
        in_ch = 32; W1 = Wc1; b1 = bc1; W2 = Wc2; b2 = bc2; out = g_iff_tar;
        if (threadIdx.x < 32) xin[threadIdx.x] = img[threadIdx.x * N_PTS + n];
    }
    __syncthreads();
    int t = threadIdx.x;
    if (t < 64) {
        float h = b1[t];
        for (int i = 0; i < in_ch; i++) h = fmaf(W1[t * in_ch + i], xin[i], h);
        hid[t] = (h > 0.0f) ? h : 0.01f * h;
    }
    __syncthreads();
    float o = b2[t];
#pragma unroll 8
    for (int j = 0; j < 64; j++) o = fmaf(W2[t * 64 + j], hid[j], o);
    out[t * N_PTS + n] = o;
}

// ------------- global softmax numerators + denominator (2 tasks) ----------
__global__ void softmax_kernel(const float* __restrict__ cloud,
                               const float* __restrict__ cloud_tar) {
    int task = blockIdx.x;
    const int* inds = (task == 0) ? g_inds : g_inds_self;
    const float* refc = (task == 0) ? cloud : cloud_tar;
    float* wout = (task == 0) ? g_wct : g_wcc;
    float local = 0.0f;
    for (int j = threadIdx.x; j < N_PTS * K12; j += blockDim.x) {
        int q = j / K12;
        int r = inds[j];
        float dx = cloud_tar[q * 3 + 0] - refc[r * 3 + 0];
        float dy = cloud_tar[q * 3 + 1] - refc[r * 3 + 1];
        float dz = cloud_tar[q * 3 + 2] - refc[r * 3 + 2];
        float d = sqrtf(dx * dx + dy * dy + dz * dz + 1e-12f);
        float e = expf(-d);
        wout[j] = e;
        local += e;
    }
    __shared__ float red[512];
    red[threadIdx.x] = local;
    __syncthreads();
    for (int s = 256; s > 0; s >>= 1) {
        if (threadIdx.x < s) red[threadIdx.x] += red[threadIdx.x + s];
        __syncthreads();
    }
    if (threadIdx.x == 0) g_sum[task] = red[0];
}

// ------- weighted gather-maxpool #1: img_diff / cloud_diff ---------------
__global__ void pool1_kernel() {
    int n = blockIdx.x;
    __shared__ int si[K12];
    __shared__ float sw[K12];
    float inv = 1.0f / g_sum[0];
    if (threadIdx.x < K12) {
        si[threadIdx.x] = g_inds[n * K12 + threadIdx.x];
        sw[threadIdx.x] = g_wct[n * K12 + threadIdx.x] * inv;
    }
    __syncthreads();
    int ch = threadIdx.x;  // 0..127
    float mi = -CUDART_INF_F, mp = -CUDART_INF_F;
#pragma unroll
    for (int k = 0; k < K12; k++) {
        int i = si[k];
        float wk = sw[k];
        mi = fmaxf(mi, g_iff_tar[ch * N_PTS + i] * wk);
        mp = fmaxf(mp, g_ctf[ch * N_PTS + i] * wk);
    }
    g_A[ch * N_PTS + n] = g_iff_cur[ch * N_PTS + n] - mi;  // img_diff
    g_B[ch * N_PTS + n] = g_cf[ch * N_PTS + n] - mp;       // cloud_diff
}

// ------- weighted gather-maxpool #2: spd / sid ---------------------------
__global__ void pool2_kernel() {
    int n = blockIdx.x;
    __shared__ int si[K12];
    __shared__ float sw[K12];
    float inv = 1.0f / g_sum[1];
    if (threadIdx.x < K12) {
        si[threadIdx.x] = g_inds_self[n * K12 + threadIdx.x];
        sw[threadIdx.x] = g_wcc[n * K12 + threadIdx.x] * inv;
    }
    __syncthreads();
    int ch = threadIdx.x;
    float mspd = -CUDART_INF_F, msid = -CUDART_INF_F;
#pragma unroll
    for (int k = 0; k < K12; k++) {
        int i = si[k];
        float wk = sw[k];
        mspd = fmaxf(mspd, g_B[ch * N_PTS + i] * wk);  // cloud_diff gathered
        msid = fmaxf(msid, g_A[ch * N_PTS + i] * wk);  // img_diff gathered
    }
    g_A[(128 + ch) * N_PTS + n] = mspd;  // spd
    g_B[(128 + ch) * N_PTS + n] = msid;  // sid
}

// ---------------- generic small SGEMM: Y = W @ X + b (opt lrelu) ----------
#define BM 64
#define BN 64
#define BK 16
__global__ void gemm_kernel(const float* __restrict__ W, const float* __restrict__ bias,
                            int xid, int yid, int M, int K, int N, int act) {
    const float* X = buf_ptr(xid);
    float* Y = buf_ptr(yid);
    __shared__ float Ws[BK][BM];
    __shared__ float Xs[BK][BN];
    int tid = threadIdx.x;  // 256 threads
    int m0 = blockIdx.y * BM, n0 = blockIdx.x * BN;
    int ty = tid >> 4, tx = tid & 15;
    float acc[4][4] = {};
    for (int k0 = 0; k0 < K; k0 += BK) {
#pragma unroll
        for (int i = 0; i < 4; i++) {
            int l = tid * 4 + i;
            int row = l >> 4, col = l & 15;
            float v = 0.0f;
            if (m0 + row < M) v = W[(m0 + row) * K + k0 + col];
            Ws[col][row] = v;
        }
#pragma unroll
        for (int i = 0; i < 4; i++) {
            int l = tid + i * 256;
            int kr = l >> 6, col = l & 63;
            float v = 0.0f;
            if (n0 + col < N) v = X[(k0 + kr) * N + n0 + col];
            Xs[kr][col] = v;
        }
        __syncthreads();
#pragma unroll
        for (int kk = 0; kk < BK; kk++) {
            float4 a4 = *(const float4*)&Ws[kk][ty * 4];
            float4 b4 = *(const float4*)&Xs[kk][tx * 4];
            float a[4] = {a4.x, a4.y, a4.z, a4.w};
            float bb[4] = {b4.x, b4.y, b4.z, b4.w};
#pragma unroll
            for (int i = 0; i < 4; i++)
#pragma unroll
                for (int j = 0; j < 4; j++)
                    acc[i][j] = fmaf(a[i], bb[j], acc[i][j]);
        }
        __syncthreads();
    }
#pragma unroll
    for (int i = 0; i < 4; i++) {
        int m = m0 + ty * 4 + i;
        if (m >= M) continue;
        float bv = bias[m];
#pragma unroll
        for (int j = 0; j < 4; j++) {
            int n = n0 + tx * 4 + j;
            if (n >= N) continue;
            float v = acc[i][j] + bv;
            if (act) v = (v > 0.0f) ? v : 0.01f * v;
            Y[m * N + n] = v;
        }
    }
}

// ---------------- final: current + mean_k(target*x)[inds_pp] --------------
__global__ void final_kernel(const float* __restrict__ cur,
                             const float* __restrict__ tgt,
                             float* __restrict__ out) {
    int n = blockIdx.x;
    __shared__ int i4[KPP];
    if (threadIdx.x < KPP) i4[threadIdx.x] = g_inds_pp[n * KPP + threadIdx.x];
    __syncthreads();
    int t = threadIdx.x;  // 0..159
    float s = 0.0f;
#pragma unroll
    for (int k = 0; k < KPP; k++) {
        int i = i4[k];
        s += tgt[t * N_PTS + i] * g_X3[t * N_PTS + i];
    }
    out[t * N_PTS + n] = cur[t * N_PTS + n] + 0.25f * s;
}

// --------------------------------------------------------------------------
extern "C" void kernel_launch(void* const* d_in, const int* in_sizes, int n_in,
                              void* d_out, int out_size) {
    const float* img       = (const float*)d_in[0];
    const float* cloud     = (const float*)d_in[1];
    const float* img_tar   = (const float*)d_in[2];
    const float* cloud_tar = (const float*)d_in[3];
    const float* cur_feat  = (const float*)d_in[4];
    const float* tgt_feat  = (const float*)d_in[5];
    const float* Wc1 = (const float*)d_in[6],  *bc1 = (const float*)d_in[7];
    const float* Wc2 = (const float*)d_in[8],  *bc2 = (const float*)d_in[9];
    const float* Wp1 = (const float*)d_in[10], *bp1 = (const float*)d_in[11];
    const float* Wp2 = (const float*)d_in[12], *bp2 = (const float*)d_in[13];
    const float* Wfc1 = (const float*)d_in[14], *bfc1 = (const float*)d_in[15];
    const float* Wfc2 = (const float*)d_in[16], *bfc2 = (const float*)d_in[17];
    const float* Wfu2 = (const float*)d_in[18], *bfu2 = (const float*)d_in[19];
    const float* Wpn1 = (const float*)d_in[20], *bpn1 = (const float*)d_in[21];
    const float* Wpn2 = (const float*)d_in[22], *bpn2 = (const float*)d_in[23];
    const float* Wpn3 = (const float*)d_in[24], *bpn3 = (const float*)d_in[25];
    float* out = (float*)d_out;

    // KNN (3 searches)
    knn_kernel<K12><<<4, 128>>>(cloud, cloud_tar, 0);      // inds
    knn_kernel<K12><<<4, 128>>>(cloud_tar, cloud_tar, 1);  // inds_self
    knn_kernel<KPP><<<4, 128>>>(cloud_tar, cloud, 2);      // inds_pp

    // Point / image features (4 tasks fused)
    feat_kernel<<<dim3(N_PTS, 4), 128>>>(img, img_tar, cloud, cloud_tar,
                                         Wc1, bc1, Wc2, bc2, Wp1, bp1, Wp2, bp2);

    // Global softmax weights (2 tasks)
    softmax_kernel<<<2, 512>>>(cloud, cloud_tar);

    // Weighted gather-maxpools
    pool1_kernel<<<N_PTS, 128>>>();
    pool2_kernel<<<N_PTS, 128>>>();

    // GEMM chain
    dim3 gN((N_PTS + BN - 1) / BN, 1);
    gN.y = 1;  gemm_kernel<<<dim3(8, 1), 256>>>(Wfc2, bfc2, 1, 2, 64, 256, N_PTS, 0);   // fuse_p
               gemm_kernel<<<dim3(8, 1), 256>>>(Wfc1, bfc1, 0, 7, 64, 256, N_PTS, 0);   // fuse_i
               gemm_kernel<<<dim3(8, 3), 256>>>(Wfu2, bfu2, 2, 3, 160, 128, N_PTS, 0);  // fuse_t_c
               gemm_kernel<<<dim3(8, 4), 256>>>(Wpn1, bpn1, 3, 4, 256, 160, N_PTS, 0);  // pn1
               gemm_kernel<<<dim3(8, 16), 256>>>(Wpn2, bpn2, 4, 5, 1024, 256, N_PTS, 1);// pn2+lrelu
               gemm_kernel<<<dim3(8, 3), 256>>>(Wpn3, bpn3, 5, 6, 160, 1024, N_PTS, 0); // pn3

    // Final gather-mean
    final_kernel<<<N_PTS, 160>>>(cur_feat, tgt_feat, out);
}

// round 2
// speedup vs baseline: 1.3231x; 1.3231x over previous
#include <cuda_runtime.h>
#include <math_constants.h>

#define N_PTS 500
#define K12 12
#define KPP 4

// ---------------- scratch (device globals; no allocation) ----------------
// Point-major feature buffers (n*128 + ch) for coalesced neighbor gathers.
__device__ float g_cfT[N_PTS * 128];   // pfeat(cloud_tar)
__device__ float g_ctfT[N_PTS * 128];  // pfeat(cloud)
__device__ float g_icT[N_PTS * 128];   // ifeat(img_tar)  (= iff on current)
__device__ float g_itT[N_PTS * 128];   // ifeat(img)      (= iff on target)
__device__ int   g_inds[N_PTS * K12];
__device__ int   g_inds_self[N_PTS * K12];
__device__ int   g_inds_pp[N_PTS * KPP];
__device__ float g_wct[N_PTS * K12];
__device__ float g_wcc[N_PTS * K12];
__device__ float g_sum[2];
// Point-major concat matrices (n*256 + c)
__device__ float g_AT[N_PTS * 256];    // [img_diff ; spd]
__device__ float g_BT[N_PTS * 256];    // [cloud_diff ; sid]
// Channel-major GEMM chain buffers
__device__ float g_C[128 * N_PTS];     // [fuse_p ; fuse_i]
__device__ float g_F[160 * N_PTS];
__device__ float g_X1[256 * N_PTS];
__device__ float g_X2[1024 * N_PTS];
__device__ float g_X3[160 * N_PTS];

__device__ __forceinline__ float* buf_ptr(int id) {
    switch (id) {
        case 0: return g_AT;
        case 1: return g_BT;
        case 2: return g_C;
        case 3: return g_F;
        case 4: return g_X1;
        case 5: return g_X2;
        case 6: return g_X3;
        case 7: return g_C + 64 * N_PTS;
    }
    return nullptr;
}

// ---------------- KNN ----------------------------------------------------
// Matches jax.lax.top_k(-d2, k): strict '<' acceptance + strict '<' bubble.
__global__ void knn12_kernel(const float* __restrict__ cloud,
                             const float* __restrict__ cloud_tar) {
    int task = blockIdx.y;  // 0: ref=cloud -> g_inds ; 1: ref=cloud_tar -> g_inds_self
    const float* ref = task ? cloud_tar : cloud;
    int* out = task ? g_inds_self : g_inds;
    __shared__ float rx[N_PTS], ry[N_PTS], rz[N_PTS], rr[N_PTS];
    for (int i = threadIdx.x; i < N_PTS; i += blockDim.x) {
        float x = ref[i * 3 + 0], y = ref[i * 3 + 1], z = ref[i * 3 + 2];
        rx[i] = x; ry[i] = y; rz[i] = z;
        rr[i] = x * x + y * y + z * z;
    }
    __syncthreads();
    int q = blockIdx.x * blockDim.x + threadIdx.x;
    if (q >= N_PTS) return;
    float qx = cloud_tar[q * 3 + 0], qy = cloud_tar[q * 3 + 1], qz = cloud_tar[q * 3 + 2];
    float qq = qx * qx + qy * qy + qz * qz;
    float dist[K12]; int idx[K12];
#pragma unroll
    for (int t = 0; t < K12; t++) { dist[t] = CUDART_INF_F; idx[t] = 0; }
    for (int r = 0; r < N_PTS; r++) {
        float d2 = qq - 2.0f * (qx * rx[r] + qy * ry[r] + qz * rz[r]) + rr[r];
        if (d2 < dist[K12 - 1]) {
            dist[K12 - 1] = d2; idx[K12 - 1] = r;
#pragma unroll
            for (int t = K12 - 1; t > 0; --t) {
                if (dist[t] < dist[t - 1]) {
                    float td = dist[t]; dist[t] = dist[t - 1]; dist[t - 1] = td;
                    int ti = idx[t]; idx[t] = idx[t - 1]; idx[t - 1] = ti;
                }
            }
        }
    }
#pragma unroll
    for (int t = 0; t < K12; t++) out[q * K12 + t] = idx[t];
}

__global__ void knn4_kernel(const float* __restrict__ cloud,
                            const float* __restrict__ cloud_tar) {
    // ref = cloud_tar, query = cloud -> g_inds_pp
    __shared__ float rx[N_PTS], ry[N_PTS], rz[N_PTS], rr[N_PTS];
    for (int i = threadIdx.x; i < N_PTS; i += blockDim.x) {
        float x = cloud_tar[i * 3 + 0], y = cloud_tar[i * 3 + 1], z = cloud_tar[i * 3 + 2];
        rx[i] = x; ry[i] = y; rz[i] = z;
        rr[i] = x * x + y * y + z * z;
    }
    __syncthreads();
    int q = blockIdx.x * blockDim.x + threadIdx.x;
    if (q >= N_PTS) return;
    float qx = cloud[q * 3 + 0], qy = cloud[q * 3 + 1], qz = cloud[q * 3 + 2];
    float qq = qx * qx + qy * qy + qz * qz;
    float dist[KPP]; int idx[KPP];
#pragma unroll
    for (int t = 0; t < KPP; t++) { dist[t] = CUDART_INF_F; idx[t] = 0; }
    for (int r = 0; r < N_PTS; r++) {
        float d2 = qq - 2.0f * (qx * rx[r] + qy * ry[r] + qz * rz[r]) + rr[r];
        if (d2 < dist[KPP - 1]) {
            dist[KPP - 1] = d2; idx[KPP - 1] = r;
#pragma unroll
            for (int t = KPP - 1; t > 0; --t) {
                if (dist[t] < dist[t - 1]) {
                    float td = dist[t]; dist[t] = dist[t - 1]; dist[t - 1] = td;
                    int ti = idx[t]; idx[t] = idx[t - 1]; idx[t - 1] = ti;
                }
            }
        }
    }
#pragma unroll
    for (int t = 0; t < KPP; t++) g_inds_pp[q * KPP + t] = idx[t];
}

// ---------------- fused 2-layer 1x1 conv features (tiled, 4 tasks) --------
// 32 points per block, W2 in smem, 16 output channels per thread.
// Writes POINT-MAJOR: out[n*128 + ch].
__global__ void feat_kernel(const float* __restrict__ img,
                            const float* __restrict__ img_tar,
                            const float* __restrict__ cloud,
                            const float* __restrict__ cloud_tar,
                            const float* __restrict__ Wc1, const float* __restrict__ bc1,
                            const float* __restrict__ Wc2, const float* __restrict__ bc2,
                            const float* __restrict__ Wp1, const float* __restrict__ bp1,
                            const float* __restrict__ Wp2, const float* __restrict__ bp2) {
    __shared__ float W2s[128 * 64];  // 32 KB
    __shared__ float xin[32 * 32];   // [c][pt]
    __shared__ float hid[64 * 32];   // [c][pt]
    int task = blockIdx.y;
    int n0 = blockIdx.x * 32;
    int tid = threadIdx.x;  // 256
    const float *W1, *b1, *W2, *b2;
    float* out;
    int in_ch;
    if (task < 2) {
        in_ch = 3; W1 = Wp1; b1 = bp1; W2 = Wp2; b2 = bp2;
        out = task ? g_ctfT : g_cfT;
        const float* src = task ? cloud : cloud_tar;
        for (int i = tid; i < 3 * 32; i += 256) {
            int c = i >> 5, p = i & 31;
            xin[i] = (n0 + p < N_PTS) ? src[(n0 + p) * 3 + c] : 0.0f;
        }
    } else {
        in_ch = 32; W1 = Wc1; b1 = bc1; W2 = Wc2; b2 = bc2;
        out = (task == 2) ? g_icT : g_itT;
        const float* src = (task == 2) ? img_tar : img;
        for (int i = tid; i < 32 * 32; i += 256) {
            int c = i >> 5, p = i & 31;
            xin[i] = (n0 + p < N_PTS) ? src[c * N_PTS + n0 + p] : 0.0f;
        }
    }
    for (int i = tid; i < 128 * 64 / 4; i += 256)
        ((float4*)W2s)[i] = ((const float4*)W2)[i];
    __syncthreads();

    int pt = tid & 31, g = tid >> 5;  // g: 0..7
    for (int cc = 0; cc < 8; cc++) {
        int ch = g * 8 + cc;
        float h = b1[ch];
        for (int i = 0; i < in_ch; i++)
            h = fmaf(W1[ch * in_ch + i], xin[i * 32 + pt], h);
        hid[ch * 32 + pt] = (h > 0.0f) ? h : 0.01f * h;
    }
    __syncthreads();

    int ch0 = g * 16;
    float acc[16];
#pragma unroll
    for (int i = 0; i < 16; i++) acc[i] = b2[ch0 + i];
#pragma unroll 4
    for (int j = 0; j < 64; j++) {
        float h = hid[j * 32 + pt];
#pragma unroll
        for (int i = 0; i < 16; i++)
            acc[i] = fmaf(W2s[(ch0 + i) * 64 + j], h, acc[i]);
    }
    int n = n0 + pt;
    if (n < N_PTS) {
#pragma unroll
        for (int i = 0; i < 16; i++) out[n * 128 + ch0 + i] = acc[i];
    }
}

// ------------- global softmax numerators + denominator (2 tasks) ----------
__global__ void softmax_kernel(const float* __restrict__ cloud,
                               const float* __restrict__ cloud_tar) {
    int task = blockIdx.x;
    const int* inds = (task == 0) ? g_inds : g_inds_self;
    const float* refc = (task == 0) ? cloud : cloud_tar;
    float* wout = (task == 0) ? g_wct : g_wcc;
    float local = 0.0f;
    for (int j = threadIdx.x; j < N_PTS * K12; j += blockDim.x) {
        int q = j / K12;
        int r = inds[j];
        float dx = cloud_tar[q * 3 + 0] - refc[r * 3 + 0];
        float dy = cloud_tar[q * 3 + 1] - refc[r * 3 + 1];
        float dz = cloud_tar[q * 3 + 2] - refc[r * 3 + 2];
        float d = sqrtf(dx * dx + dy * dy + dz * dz + 1e-12f);
        float e = expf(-d);
        wout[j] = e;
        local += e;
    }
    __shared__ float red[512];
    red[threadIdx.x] = local;
    __syncthreads();
    for (int s = 256; s > 0; s >>= 1) {
        if (threadIdx.x < s) red[threadIdx.x] += red[threadIdx.x + s];
        __syncthreads();
    }
    if (threadIdx.x == 0) g_sum[task] = red[0];
}

// ------- pool1: img_diff / cloud_diff (coalesced point-major gathers) -----
__global__ void pool1_kernel() {
    int n = blockIdx.x;
    int ch = threadIdx.x;  // 0..127
    __shared__ int si[K12];
    __shared__ float sw[K12];
    if (ch < K12) {
        si[ch] = g_inds[n * K12 + ch];
        sw[ch] = g_wct[n * K12 + ch] * (1.0f / g_sum[0]);
    }
    __syncthreads();
    float mi = -CUDART_INF_F, mp = -CUDART_INF_F;
#pragma unroll
    for (int k = 0; k < K12; k++) {
        int i = si[k];
        float w = sw[k];
        mi = fmaxf(mi, g_itT[i * 128 + ch] * w);
        mp = fmaxf(mp, g_ctfT[i * 128 + ch] * w);
    }
    g_AT[n * 256 + ch] = g_icT[n * 128 + ch] - mi;  // img_diff
    g_BT[n * 256 + ch] = g_cfT[n * 128 + ch] - mp;  // cloud_diff
}

// ------- pool2: spd / sid -------------------------------------------------
__global__ void pool2_kernel() {
    int n = blockIdx.x;
    int ch = threadIdx.x;  // 0..127
    __shared__ int si[K12];
    __shared__ float sw[K12];
    if (ch < K12) {
        si[ch] = g_inds_self[n * K12 + ch];
        sw[ch] = g_wcc[n * K12 + ch] * (1.0f / g_sum[1]);
    }
    __syncthreads();
    float mspd = -CUDART_INF_F, msid = -CUDART_INF_F;
#pragma unroll
    for (int k = 0; k < K12; k++) {
        int i = si[k];
        float w = sw[k];
        mspd = fmaxf(mspd, g_BT[i * 256 + ch] * w);  // cloud_diff gathered
        msid = fmaxf(msid, g_AT[i * 256 + ch] * w);  // img_diff gathered
    }
    g_AT[n * 256 + 128 + ch] = mspd;  // spd
    g_BT[n * 256 + 128 + ch] = msid;  // sid
}

// ---------------- generic small SGEMM: Y = W @ X + b (opt lrelu) ----------
// xT=1: X is point-major XT[n*K + k] (used for the concat matrices).
#define BM 64
#define BN 64
#define BK 16
__global__ void gemm_kernel(const float* __restrict__ W, const float* __restrict__ bias,
                            int xid, int yid, int M, int K, int N, int act, int xT) {
    const float* X = buf_ptr(xid);
    float* Y = buf_ptr(yid);
    __shared__ float Ws[BK][BM];
    __shared__ float Xs[BK][BN];
    int tid = threadIdx.x;  // 256
    int m0 = blockIdx.y * BM, n0 = blockIdx.x * BN;
    int ty = tid >> 4, tx = tid & 15;
    float acc[4][4] = {};
    for (int k0 = 0; k0 < K; k0 += BK) {
#pragma unroll
        for (int i = 0; i < 4; i++) {
            int l = tid * 4 + i;
            int row = l >> 4, col = l & 15;
            float v = 0.0f;
            if (m0 + row < M) v = W[(m0 + row) * K + k0 + col];
            Ws[col][row] = v;
        }
        if (xT) {
#pragma unroll
            for (int i = 0; i < 4; i++) {
                int l = tid + i * 256;
                int kr = l & 15, col = l >> 4;
                float v = 0.0f;
                if (n0 + col < N) v = X[(n0 + col) * K + k0 + kr];
                Xs[kr][col] = v;
            }
        } else {
#pragma unroll
            for (int i = 0; i < 4; i++) {
                int l = tid + i * 256;
                int kr = l >> 6, col = l & 63;
                float v = 0.0f;
                if (n0 + col < N) v = X[(k0 + kr) * N + n0 + col];
                Xs[kr][col] = v;
            }
        }
        __syncthreads();
#pragma unroll
        for (int kk = 0; kk < BK; kk++) {
            float4 a4 = *(const float4*)&Ws[kk][ty * 4];
            float4 b4 = *(const float4*)&Xs[kk][tx * 4];
            float a[4] = {a4.x, a4.y, a4.z, a4.w};
            float bb[4] = {b4.x, b4.y, b4.z, b4.w};
#pragma unroll
            for (int i = 0; i < 4; i++)
#pragma unroll
                for (int j = 0; j < 4; j++)
                    acc[i][j] = fmaf(a[i], bb[j], acc[i][j]);
        }
        __syncthreads();
    }
#pragma unroll
    for (int i = 0; i < 4; i++) {
        int m = m0 + ty * 4 + i;
        if (m >= M) continue;
        float bv = bias[m];
#pragma unroll
        for (int j = 0; j < 4; j++) {
            int n = n0 + tx * 4 + j;
            if (n >= N) continue;
            float v = acc[i][j] + bv;
            if (act) v = (v > 0.0f) ? v : 0.01f * v;
            Y[m * N + n] = v;
        }
    }
}

// ---------------- final: current + mean_k(target*x)[inds_pp] --------------
__global__ void final_kernel(const float* __restrict__ cur,
                             const float* __restrict__ tgt,
                             float* __restrict__ out) {
    int n = blockIdx.x;
    __shared__ int i4[KPP];
    if (threadIdx.x < KPP) i4[threadIdx.x] = g_inds_pp[n * KPP + threadIdx.x];
    __syncthreads();
    int t = threadIdx.x;  // 0..159
    float s = 0.0f;
#pragma unroll
    for (int k = 0; k < KPP; k++) {
        int i = i4[k];
        s += tgt[t * N_PTS + i] * g_X3[t * N_PTS + i];
    }
    out[t * N_PTS + n] = cur[t * N_PTS + n] + 0.25f * s;
}

// --------------------------------------------------------------------------
extern "C" void kernel_launch(void* const* d_in, const int* in_sizes, int n_in,
                              void* d_out, int out_size) {
    const float* img       = (const float*)d_in[0];
    const float* cloud     = (const float*)d_in[1];
    const float* img_tar   = (const float*)d_in[2];
    const float* cloud_tar = (const float*)d_in[3];
    const float* cur_feat  = (const float*)d_in[4];
    const float* tgt_feat  = (const float*)d_in[5];
    const float* Wc1 = (const float*)d_in[6],  *bc1 = (const float*)d_in[7];
    const float* Wc2 = (const float*)d_in[8],  *bc2 = (const float*)d_in[9];
    const float* Wp1 = (const float*)d_in[10], *bp1 = (const float*)d_in[11];
    const float* Wp2 = (const float*)d_in[12], *bp2 = (const float*)d_in[13];
    const float* Wfc1 = (const float*)d_in[14], *bfc1 = (const float*)d_in[15];
    const float* Wfc2 = (const float*)d_in[16], *bfc2 = (const float*)d_in[17];
    const float* Wfu2 = (const float*)d_in[18], *bfu2 = (const float*)d_in[19];
    const float* Wpn1 = (const float*)d_in[20], *bpn1 = (const float*)d_in[21];
    const float* Wpn2 = (const float*)d_in[22], *bpn2 = (const float*)d_in[23];
    const float* Wpn3 = (const float*)d_in[24], *bpn3 = (const float*)d_in[25];
    float* out = (float*)d_out;

    knn12_kernel<<<dim3(4, 2), 128>>>(cloud, cloud_tar);
    knn4_kernel<<<4, 128>>>(cloud, cloud_tar);

    feat_kernel<<<dim3(16, 4), 256>>>(img, img_tar, cloud, cloud_tar,
                                      Wc1, bc1, Wc2, bc2, Wp1, bp1, Wp2, bp2);

    softmax_kernel<<<2, 512>>>(cloud, cloud_tar);
    pool1_kernel<<<N_PTS, 128>>>();
    pool2_kernel<<<N_PTS, 128>>>();

    gemm_kernel<<<dim3(8, 1), 256>>>(Wfc2, bfc2, 1, 2, 64, 256, N_PTS, 0, 1);    // fuse_p
    gemm_kernel<<<dim3(8, 1), 256>>>(Wfc1, bfc1, 0, 7, 64, 256, N_PTS, 0, 1);    // fuse_i
    gemm_kernel<<<dim3(8, 3), 256>>>(Wfu2, bfu2, 2, 3, 160, 128, N_PTS, 0, 0);   // fuse_t_c
    gemm_kernel<<<dim3(8, 4), 256>>>(Wpn1, bpn1, 3, 4, 256, 160, N_PTS, 0, 0);   // pn1
    gemm_kernel<<<dim3(8, 16), 256>>>(Wpn2, bpn2, 4, 5, 1024, 256, N_PTS, 1, 0); // pn2+lrelu
    gemm_kernel<<<dim3(8, 3), 256>>>(Wpn3, bpn3, 5, 6, 160, 1024, N_PTS, 0, 0);  // pn3

    final_kernel<<<N_PTS, 160>>>(cur_feat, tgt_feat, out);
}

// round 3
// speedup vs baseline: 1.6774x; 1.2678x over previous
#include <cuda_runtime.h>
#include <math_constants.h>

#define N_PTS 500
#define K12 12
#define KPP 4
#define NBLK 128
#define NTHR 256

// ---------------- scratch (device globals; no allocation) ----------------
__device__ float g_cfT[N_PTS * 128];   // pfeat(cloud_tar)     point-major
__device__ float g_ctfT[N_PTS * 128];  // pfeat(cloud)
__device__ float g_icT[N_PTS * 128];   // ifeat(img_tar)
__device__ float g_itT[N_PTS * 128];   // ifeat(img)
__device__ int   g_inds[N_PTS * K12];
__device__ int   g_inds_self[N_PTS * K12];
__device__ int   g_inds_pp[N_PTS * KPP];
__device__ float g_wct[N_PTS * K12];
__device__ float g_wcc[N_PTS * K12];
__device__ float g_sum[2];
__device__ float g_AT[N_PTS * 256];    // [img_diff ; spd]  point-major
__device__ float g_BT[N_PTS * 256];    // [cloud_diff ; sid] point-major
__device__ float g_C[128 * N_PTS];     // [fuse_p ; fuse_i]  channel-major
__device__ float g_F[160 * N_PTS];
__device__ float g_X1[256 * N_PTS];
__device__ float g_X2[1024 * N_PTS];
__device__ float g_X3[160 * N_PTS];

// ---------------- grid barrier (replay-safe) ------------------------------
__device__ unsigned g_bar_count[16];
__device__ unsigned g_bar_gen[16];

__device__ __forceinline__ void gridbar(int slot) {
    __syncthreads();
    if (threadIdx.x == 0) {
        __threadfence();
        unsigned gen = *((volatile unsigned*)&g_bar_gen[slot]);
        unsigned t = atomicAdd(&g_bar_count[slot], 1u);
        if (t == (unsigned)(gridDim.x - 1)) {
            g_bar_count[slot] = 0;
            __threadfence();
            atomicAdd(&g_bar_gen[slot], 1u);
        } else {
            while (*((volatile unsigned*)&g_bar_gen[slot]) == gen) {}
        }
        __threadfence();
    }
    __syncthreads();
}

// ---------------- shared memory union -------------------------------------
struct SmemKNN { float rx[N_PTS], ry[N_PTS], rz[N_PTS], rr[N_PTS]; };
struct SmemFeat { float W2s[128 * 64]; float xin[32 * 32]; float hid[64 * 32]; };
struct SmemGemm { float Ws[16][64]; float Xs[16][64]; };
struct SmemRed { float red[NTHR]; };
union __align__(16) Smem {
    SmemKNN knn;
    SmemFeat feat;
    SmemGemm gemm;
    SmemRed red;
};

// ---------------- KNN (per-thread insertion sort, matches lax.top_k ties) --
template <int K>
__device__ void dev_knn(const float* __restrict__ ref, const float* __restrict__ query,
                        int* __restrict__ outIdx, int qbase, Smem& sm) {
    for (int i = threadIdx.x; i < N_PTS; i += NTHR) {
        float x = ref[i * 3 + 0], y = ref[i * 3 + 1], z = ref[i * 3 + 2];
        sm.knn.rx[i] = x; sm.knn.ry[i] = y; sm.knn.rz[i] = z;
        sm.knn.rr[i] = x * x + y * y + z * z;
    }
    __syncthreads();
    int q = qbase + threadIdx.x;
    if (q >= N_PTS) return;
    float qx = query[q * 3 + 0], qy = query[q * 3 + 1], qz = query[q * 3 + 2];
    float qq = qx * qx + qy * qy + qz * qz;
    float dist[K]; int idx[K];
#pragma unroll
    for (int t = 0; t < K; t++) { dist[t] = CUDART_INF_F; idx[t] = 0; }
    for (int r = 0; r < N_PTS; r++) {
        float d2 = qq - 2.0f * (qx * sm.knn.rx[r] + qy * sm.knn.ry[r] + qz * sm.knn.rz[r])
                 + sm.knn.rr[r];
        if (d2 < dist[K - 1]) {
            dist[K - 1] = d2; idx[K - 1] = r;
#pragma unroll
            for (int t = K - 1; t > 0; --t) {
                if (dist[t] < dist[t - 1]) {
                    float td = dist[t]; dist[t] = dist[t - 1]; dist[t - 1] = td;
                    int ti = idx[t]; idx[t] = idx[t - 1]; idx[t - 1] = ti;
                }
            }
        }
    }
#pragma unroll
    for (int t = 0; t < K; t++) outIdx[q * K + t] = idx[t];
}

// ---------------- feature tile (2-layer 1x1 conv), point-major out --------
__device__ void dev_feat(int featb,
                         const float* __restrict__ img, const float* __restrict__ img_tar,
                         const float* __restrict__ cloud, const float* __restrict__ cloud_tar,
                         const float* __restrict__ Wc1, const float* __restrict__ bc1,
                         const float* __restrict__ Wc2, const float* __restrict__ bc2,
                         const float* __restrict__ Wp1, const float* __restrict__ bp1,
                         const float* __restrict__ Wp2, const float* __restrict__ bp2,
                         Smem& sm) {
    int task = featb >> 4;
    int n0 = (featb & 15) * 32;
    int tid = threadIdx.x;
    const float *W1, *b1, *W2, *b2;
    float* out;
    int in_ch;
    if (task < 2) {
        in_ch = 3; W1 = Wp1; b1 = bp1; W2 = Wp2; b2 = bp2;
        out = task ? g_ctfT : g_cfT;
        const float* src = task ? cloud : cloud_tar;
        for (int i = tid; i < 3 * 32; i += NTHR) {
            int c = i >> 5, p = i & 31;
            sm.feat.xin[i] = (n0 + p < N_PTS) ? src[(n0 + p) * 3 + c] : 0.0f;
        }
    } else {
        in_ch = 32; W1 = Wc1; b1 = bc1; W2 = Wc2; b2 = bc2;
        out = (task == 2) ? g_icT : g_itT;
        const float* src = (task == 2) ? img_tar : img;
        for (int i = tid; i < 32 * 32; i += NTHR) {
            int c = i >> 5, p = i & 31;
            sm.feat.xin[i] = (n0 + p < N_PTS) ? src[c * N_PTS + n0 + p] : 0.0f;
        }
    }
    for (int i = tid; i < 128 * 64 / 4; i += NTHR)
        ((float4*)sm.feat.W2s)[i] = ((const float4*)W2)[i];
    __syncthreads();

    int pt = tid & 31, g = tid >> 5;
    for (int cc = 0; cc < 8; cc++) {
        int ch = g * 8 + cc;
        float h = b1[ch];
        for (int i = 0; i < in_ch; i++)
            h = fmaf(W1[ch * in_ch + i], sm.feat.xin[i * 32 + pt], h);
        sm.feat.hid[ch * 32 + pt] = (h > 0.0f) ? h : 0.01f * h;
    }
    __syncthreads();

    int ch0 = g * 16;
    float acc[16];
#pragma unroll
    for (int i = 0; i < 16; i++) acc[i] = b2[ch0 + i];
#pragma unroll 4
    for (int j = 0; j < 64; j++) {
        float h = sm.feat.hid[j * 32 + pt];
#pragma unroll
        for (int i = 0; i < 16; i++)
            acc[i] = fmaf(sm.feat.W2s[(ch0 + i) * 64 + j], h, acc[i]);
    }
    int n = n0 + pt;
    if (n < N_PTS) {
#pragma unroll
        for (int i = 0; i < 16; i++) out[n * 128 + ch0 + i] = acc[i];
    }
}

// ---------------- one 64x64 GEMM tile: Y = W @ X + b ----------------------
__device__ void gemm_tile(const float* __restrict__ W, const float* __restrict__ bias,
                          const float* __restrict__ X, float* __restrict__ Y,
                          int M, int K, int N, int act, int xT, int m0, int n0, Smem& sm) {
    int tid = threadIdx.x;
    int ty = tid >> 4, tx = tid & 15;
    float acc[4][4] = {};
    for (int k0 = 0; k0 < K; k0 += 16) {
#pragma unroll
        for (int i = 0; i < 4; i++) {
            int l = tid * 4 + i;
            int row = l >> 4, col = l & 15;
            float v = 0.0f;
            if (m0 + row < M) v = W[(m0 + row) * K + k0 + col];
            sm.gemm.Ws[col][row] = v;
        }
        if (xT) {
#pragma unroll
            for (int i = 0; i < 4; i++) {
                int l = tid + i * NTHR;
                int kr = l & 15, col = l >> 4;
                float v = 0.0f;
                if (n0 + col < N) v = X[(n0 + col) * K + k0 + kr];
                sm.gemm.Xs[kr][col] = v;
            }
        } else {
#pragma unroll
            for (int i = 0; i < 4; i++) {
                int l = tid + i * NTHR;
                int kr = l >> 6, col = l & 63;
                float v = 0.0f;
                if (n0 + col < N) v = X[(k0 + kr) * N + n0 + col];
                sm.gemm.Xs[kr][col] = v;
            }
        }
        __syncthreads();
#pragma unroll
        for (int kk = 0; kk < 16; kk++) {
            float4 a4 = *(const float4*)&sm.gemm.Ws[kk][ty * 4];
            float4 b4 = *(const float4*)&sm.gemm.Xs[kk][tx * 4];
            float a[4] = {a4.x, a4.y, a4.z, a4.w};
            float bb[4] = {b4.x, b4.y, b4.z, b4.w};
#pragma unroll
            for (int i = 0; i < 4; i++)
#pragma unroll
                for (int j = 0; j < 4; j++)
                    acc[i][j] = fmaf(a[i], bb[j], acc[i][j]);
        }
        __syncthreads();
    }
#pragma unroll
    for (int i = 0; i < 4; i++) {
        int m = m0 + ty * 4 + i;
        if (m >= M) continue;
        float bv = bias[m];
#pragma unroll
        for (int j = 0; j < 4; j++) {
            int n = n0 + tx * 4 + j;
            if (n >= N) continue;
            float v = acc[i][j] + bv;
            if (act) v = (v > 0.0f) ? v : 0.01f * v;
            Y[m * N + n] = v;
        }
    }
}

__device__ __forceinline__ void gemm_phase(const float* W, const float* bias,
                                           const float* X, float* Y,
                                           int M, int K, int N, int act, int xT,
                                           int tilesM, Smem& sm) {
    int total = tilesM * 8;
    for (int t = blockIdx.x; t < total; t += NBLK)
        gemm_tile(W, bias, X, Y, M, K, N, act, xT, (t >> 3) * 64, (t & 7) * 64, sm);
}

// --------------------------- megakernel -----------------------------------
__global__ void __launch_bounds__(NTHR, 1)
mega_kernel(const float* __restrict__ img, const float* __restrict__ cloud,
            const float* __restrict__ img_tar, const float* __restrict__ cloud_tar,
            const float* __restrict__ cur_feat, const float* __restrict__ tgt_feat,
            const float* __restrict__ Wc1, const float* __restrict__ bc1,
            const float* __restrict__ Wc2, const float* __restrict__ bc2,
            const float* __restrict__ Wp1, const float* __restrict__ bp1,
            const float* __restrict__ Wp2, const float* __restrict__ bp2,
            const float* __restrict__ Wfc1, const float* __restrict__ bfc1,
            const float* __restrict__ Wfc2, const float* __restrict__ bfc2,
            const float* __restrict__ Wfu2, const float* __restrict__ bfu2,
            const float* __restrict__ Wpn1, const float* __restrict__ bpn1,
            const float* __restrict__ Wpn2, const float* __restrict__ bpn2,
            const float* __restrict__ Wpn3, const float* __restrict__ bpn3,
            float* __restrict__ out) {
    __shared__ Smem sm;
    int b = blockIdx.x;
    int tid = threadIdx.x;

    // ---- phase 0: KNN (blocks 0-5) || features (blocks 6-69) || zero sums
    if (b < 6) {
        int task = b >> 1, qbase = (b & 1) * NTHR;
        if (task == 0)      dev_knn<K12>(cloud,     cloud_tar, g_inds,      qbase, sm);
        else if (task == 1) dev_knn<K12>(cloud_tar, cloud_tar, g_inds_self, qbase, sm);
        else                dev_knn<KPP>(cloud_tar, cloud,     g_inds_pp,   qbase, sm);
    } else if (b < 70) {
        dev_feat(b - 6, img, img_tar, cloud, cloud_tar,
                 Wc1, bc1, Wc2, bc2, Wp1, bp1, Wp2, bp2, sm);
    } else if (b == 70 && tid == 0) {
        g_sum[0] = 0.0f; g_sum[1] = 0.0f;
    }
    gridbar(0);

    // ---- phase 1: softmax numerators + partial denominators (12 blocks)
    if (b < 12) {
        int task = b / 6, local = b % 6;
        const int* inds = task ? g_inds_self : g_inds;
        const float* refc = task ? cloud_tar : cloud;
        float* wout = task ? g_wcc : g_wct;
        float localsum = 0.0f;
        for (int j = local * NTHR + tid; j < N_PTS * K12; j += 6 * NTHR) {
            int q = j / K12;
            int r = inds[j];
            float dx = cloud_tar[q * 3 + 0] - refc[r * 3 + 0];
            float dy = cloud_tar[q * 3 + 1] - refc[r * 3 + 1];
            float dz = cloud_tar[q * 3 + 2] - refc[r * 3 + 2];
            float d = sqrtf(dx * dx + dy * dy + dz * dz + 1e-12f);
            float e = expf(-d);
            wout[j] = e;
            localsum += e;
        }
        sm.red.red[tid] = localsum;
        __syncthreads();
        for (int s = NTHR / 2; s > 0; s >>= 1) {
            if (tid < s) sm.red.red[tid] += sm.red.red[tid + s];
            __syncthreads();
        }
        if (tid == 0) atomicAdd(&g_sum[task], sm.red.red[0]);
    }
    gridbar(1);

    // ---- phase 2: pool1 (img_diff / cloud_diff)
    {
        float inv = 1.0f / g_sum[0];
        int sub = tid >> 7, ch = tid & 127;
        for (int n = b * 2 + sub; n < N_PTS; n += NBLK * 2) {
            float mi = -CUDART_INF_F, mp = -CUDART_INF_F;
#pragma unroll
            for (int k = 0; k < K12; k++) {
                int i = g_inds[n * K12 + k];
                float w = g_wct[n * K12 + k] * inv;
                mi = fmaxf(mi, g_itT[i * 128 + ch] * w);
                mp = fmaxf(mp, g_ctfT[i * 128 + ch] * w);
            }
            g_AT[n * 256 + ch] = g_icT[n * 128 + ch] - mi;
            g_BT[n * 256 + ch] = g_cfT[n * 128 + ch] - mp;
        }
    }
    gridbar(2);

    // ---- phase 3: pool2 (spd / sid)
    {
        float inv = 1.0f / g_sum[1];
        int sub = tid >> 7, ch = tid & 127;
        for (int n = b * 2 + sub; n < N_PTS; n += NBLK * 2) {
            float mspd = -CUDART_INF_F, msid = -CUDART_INF_F;
#pragma unroll
            for (int k = 0; k < K12; k++) {
                int i = g_inds_self[n * K12 + k];
                float w = g_wcc[n * K12 + k] * inv;
                mspd = fmaxf(mspd, g_BT[i * 256 + ch] * w);
                msid = fmaxf(msid, g_AT[i * 256 + ch] * w);
            }
            g_AT[n * 256 + 128 + ch] = mspd;
            g_BT[n * 256 + 128 + ch] = msid;
        }
    }
    gridbar(3);

    // ---- phase 4: fc2 (tiles 0-7) and fc1 (tiles 8-15), both 64x256x500 xT
    for (int t = b; t < 16; t += NBLK) {
        if (t < 8)
            gemm_tile(Wfc2, bfc2, g_BT, g_C, 64, 256, N_PTS, 0, 1, 0, (t & 7) * 64, sm);
        else
            gemm_tile(Wfc1, bfc1, g_AT, g_C + 64 * N_PTS, 64, 256, N_PTS, 0, 1, 0, (t & 7) * 64, sm);
    }
    gridbar(4);

    // ---- phase 5: fuse2  (160x128x500)
    gemm_phase(Wfu2, bfu2, g_C, g_F, 160, 128, N_PTS, 0, 0, 3, sm);
    gridbar(5);

    // ---- phase 6: pn1 (256x160x500)
    gemm_phase(Wpn1, bpn1, g_F, g_X1, 256, 160, N_PTS, 0, 0, 4, sm);
    gridbar(6);

    // ---- phase 7: pn2 (1024x256x500) + lrelu
    gemm_phase(Wpn2, bpn2, g_X1, g_X2, 1024, 256, N_PTS, 1, 0, 16, sm);
    gridbar(7);

    // ---- phase 8: pn3 (160x1024x500)
    gemm_phase(Wpn3, bpn3, g_X2, g_X3, 160, 1024, N_PTS, 0, 0, 3, sm);
    gridbar(8);

    // ---- phase 9: final gather-mean
    if (tid < 160) {
        for (int n = b; n < N_PTS; n += NBLK) {
            float s = 0.0f;
#pragma unroll
            for (int k = 0; k < KPP; k++) {
                int i = g_inds_pp[n * KPP + k];
                s += tgt_feat[tid * N_PTS + i] * g_X3[tid * N_PTS + i];
            }
            out[tid * N_PTS + n] = cur_feat[tid * N_PTS + n] + 0.25f * s;
        }
    }
}

// --------------------------------------------------------------------------
extern "C" void kernel_launch(void* const* d_in, const int* in_sizes, int n_in,
                              void* d_out, int out_size) {
    const float* img       = (const float*)d_in[0];
    const float* cloud     = (const float*)d_in[1];
    const float* img_tar   = (const float*)d_in[2];
    const float* cloud_tar = (const float*)d_in[3];
    const float* cur_feat  = (const float*)d_in[4];
    const float* tgt_feat  = (const float*)d_in[5];

    mega_kernel<<<NBLK, NTHR>>>(
        img, cloud, img_tar, cloud_tar, cur_feat, tgt_feat,
        (const float*)d_in[6],  (const float*)d_in[7],
        (const float*)d_in[8],  (const float*)d_in[9],
        (const float*)d_in[10], (const float*)d_in[11],
        (const float*)d_in[12], (const float*)d_in[13],
        (const float*)d_in[14], (const float*)d_in[15],
        (const float*)d_in[16], (const float*)d_in[17],
        (const float*)d_in[18], (const float*)d_in[19],
        (const float*)d_in[20], (const float*)d_in[21],
        (const float*)d_in[22], (const float*)d_in[23],
        (const float*)d_in[24], (const float*)d_in[25],
        (float*)d_out);
}

// round 4
// speedup vs baseline: 1.8387x; 1.0961x over previous
#include <cuda_runtime.h>
#include <math_constants.h>

#define N_PTS 500
#define K12 12
#define KPP 4
#define NBLK 256
#define NTHR 256

// ---------------- scratch (device globals; no allocation) ----------------
__device__ float g_cfT[N_PTS * 128];   // pfeat(cloud_tar)  point-major
__device__ float g_ctfT[N_PTS * 128];  // pfeat(cloud)
__device__ float g_icT[N_PTS * 128];   // ifeat(img_tar)
__device__ float g_itT[N_PTS * 128];   // ifeat(img)
__device__ int   g_inds[N_PTS * K12];
__device__ int   g_inds_self[N_PTS * K12];
__device__ int   g_inds_pp[N_PTS * KPP];
__device__ float g_wct[N_PTS * K12];
__device__ float g_wcc[N_PTS * K12];
__device__ float g_sum[2];
__device__ float g_AT[N_PTS * 256];        // [img_diff ; spd]   point-major
__device__ float g_BT[N_PTS * 256];        // [cloud_diff ; sid] point-major
__device__ float g_Cp[2 * 128 * N_PTS];    // fc split-K partials
__device__ float g_biasC[128];
__device__ float g_F[160 * N_PTS];         // fuse_t_c
__device__ float g_Weffp[2 * 1024 * 160];  // fold partials (Wpn2@Wpn1)
__device__ float g_beff[1024];             // Wpn2@bpn1 + bpn2
__device__ float g_X2[1024 * N_PTS];
__device__ float g_part[8 * 160 * N_PTS];  // pn3 split-K partials
__device__ float g_X3T[N_PTS * 160];       // tgt * x3, point-major

// ---------------- grid barrier (replay-safe) ------------------------------
__device__ unsigned g_bar_count[16];
__device__ unsigned g_bar_gen[16];

__device__ __forceinline__ void gridbar(int slot) {
    __syncthreads();
    if (threadIdx.x == 0) {
        __threadfence();
        unsigned gen = *((volatile unsigned*)&g_bar_gen[slot]);
        unsigned t = atomicAdd(&g_bar_count[slot], 1u);
        if (t == (unsigned)(gridDim.x - 1)) {
            g_bar_count[slot] = 0;
            __threadfence();
            atomicAdd(&g_bar_gen[slot], 1u);
        } else {
            while (*((volatile unsigned*)&g_bar_gen[slot]) == gen) {}
        }
        __threadfence();
    }
    __syncthreads();
}

// ---------------- shared memory union -------------------------------------
struct SmemFeat { float W2s[128 * 64]; float xin[32 * 32]; float hid[64 * 32]; };
struct SmemGemm { float Ws[16][68]; float Xs[16][68]; };
struct SmemRed { float red[NTHR]; };
union __align__(16) Smem {
    SmemFeat feat;
    SmemGemm gemm;
    SmemRed red;
};

// ---------------- warp-cooperative KNN ------------------------------------
// Exact lax.top_k(-d2) tie semantics: per-lane strict-< insertion keeps
// increasing-r order on equal d2; warp selection is lexicographic (d2, idx).
template <int K>
__device__ void knn_warp(const float* __restrict__ ref, const float* __restrict__ query,
                         int* __restrict__ out, int q) {
    int lane = threadIdx.x & 31;
    float qx = query[q * 3 + 0], qy = query[q * 3 + 1], qz = query[q * 3 + 2];
    float qq = qx * qx + qy * qy + qz * qz;
    float dist[K]; int idx[K];
#pragma unroll
    for (int t = 0; t < K; t++) { dist[t] = CUDART_INF_F; idx[t] = 0x7fffffff; }
    for (int r = lane; r < N_PTS; r += 32) {
        float rx = ref[r * 3 + 0], ry = ref[r * 3 + 1], rz = ref[r * 3 + 2];
        float rr = rx * rx + ry * ry + rz * rz;
        float d2 = qq - 2.0f * (qx * rx + qy * ry + qz * rz) + rr;
        if (d2 < dist[K - 1]) {
            dist[K - 1] = d2; idx[K - 1] = r;
#pragma unroll
            for (int t = K - 1; t > 0; --t) {
                if (dist[t] < dist[t - 1]) {
                    float td = dist[t]; dist[t] = dist[t - 1]; dist[t - 1] = td;
                    int ti = idx[t]; idx[t] = idx[t - 1]; idx[t - 1] = ti;
                }
            }
        }
    }
#pragma unroll
    for (int t = 0; t < K; t++) {
        float bd = dist[0]; int bi = idx[0];
#pragma unroll
        for (int off = 16; off > 0; off >>= 1) {
            float od = __shfl_down_sync(0xffffffffu, bd, off);
            int oi = __shfl_down_sync(0xffffffffu, bi, off);
            if (od < bd || (od == bd && oi < bi)) { bd = od; bi = oi; }
        }
        bi = __shfl_sync(0xffffffffu, bi, 0);
        if (lane == 0) out[q * K + t] = bi;
        if (idx[0] == bi) {  // unique global index -> exactly one winner lane
#pragma unroll
            for (int tt = 0; tt < K - 1; tt++) { dist[tt] = dist[tt + 1]; idx[tt] = idx[tt + 1]; }
            dist[K - 1] = CUDART_INF_F; idx[K - 1] = 0x7fffffff;
        }
    }
}

// ---------------- feature tile (2-layer 1x1 conv), point-major out --------
__device__ void dev_feat(int featb,
                         const float* __restrict__ img, const float* __restrict__ img_tar,
                         const float* __restrict__ cloud, const float* __restrict__ cloud_tar,
                         const float* __restrict__ Wc1, const float* __restrict__ bc1,
                         const float* __restrict__ Wc2, const float* __restrict__ bc2,
                         const float* __restrict__ Wp1, const float* __restrict__ bp1,
                         const float* __restrict__ Wp2, const float* __restrict__ bp2,
                         Smem& sm) {
    int task = featb >> 4;
    int n0 = (featb & 15) * 32;
    int tid = threadIdx.x;
    const float *W1, *b1, *W2, *b2;
    float* out;
    int in_ch;
    if (task < 2) {
        in_ch = 3; W1 = Wp1; b1 = bp1; W2 = Wp2; b2 = bp2;
        out = task ? g_ctfT : g_cfT;
        const float* src = task ? cloud : cloud_tar;
        for (int i = tid; i < 3 * 32; i += NTHR) {
            int c = i >> 5, p = i & 31;
            sm.feat.xin[i] = (n0 + p < N_PTS) ? src[(n0 + p) * 3 + c] : 0.0f;
        }
    } else {
        in_ch = 32; W1 = Wc1; b1 = bc1; W2 = Wc2; b2 = bc2;
        out = (task == 2) ? g_icT : g_itT;
        const float* src = (task == 2) ? img_tar : img;
        for (int i = tid; i < 32 * 32; i += NTHR) {
            int c = i >> 5, p = i & 31;
            sm.feat.xin[i] = (n0 + p < N_PTS) ? src[c * N_PTS + n0 + p] : 0.0f;
        }
    }
    for (int i = tid; i < 128 * 64 / 4; i += NTHR)
        ((float4*)sm.feat.W2s)[i] = ((const float4*)W2)[i];
    __syncthreads();

    int pt = tid & 31, g = tid >> 5;
    for (int cc = 0; cc < 8; cc++) {
        int ch = g * 8 + cc;
        float h = b1[ch];
        for (int i = 0; i < in_ch; i++)
            h = fmaf(W1[ch * in_ch + i], sm.feat.xin[i * 32 + pt], h);
        sm.feat.hid[ch * 32 + pt] = (h > 0.0f) ? h : 0.01f * h;
    }
    __syncthreads();

    int ch0 = g * 16;
    float acc[16];
#pragma unroll
    for (int i = 0; i < 16; i++) acc[i] = b2[ch0 + i];
#pragma unroll 4
    for (int j = 0; j < 64; j++) {
        float h = sm.feat.hid[j * 32 + pt];
#pragma unroll
        for (int i = 0; i < 16; i++)
            acc[i] = fmaf(sm.feat.W2s[(ch0 + i) * 64 + j], h, acc[i]);
    }
    int n = n0 + pt;
    if (n < N_PTS) {
#pragma unroll
        for (int i = 0; i < 16; i++) out[n * 128 + ch0 + i] = acc[i];
    }
    __syncthreads();
}

// ---------------- pipelined 64x64 GEMM tile -------------------------------
// XMODE: 0 = X[k*N+n]; 1 = xT X[n*KX+k]; 2 = Xa[k*N+n]+Xb[k*N+n]+biasX[k]
// OUTMODE: 0 = +bias; 1 = +bias & lrelu; 2 = raw
// WSUM: 1 -> W element = Wa[..]+Wb[..]
struct GemmX { const float* X; const float* Xb; const float* biasX; int KX; };

template <int XMODE, int OUTMODE, int WSUM>
__device__ void gemm_tile(const float* __restrict__ Wa, const float* __restrict__ Wb,
                          int KW, int kb, int kLen, GemmX gx, int N,
                          const float* __restrict__ bias, float* __restrict__ Y,
                          int M, int m0, int n0, Smem& sm) {
    int tid = threadIdx.x;
    int ty = tid >> 4, tx = tid & 15;
    float acc[4][4] = {};
    float pw[4], px[4];

    auto loadW = [&](int k0) {
#pragma unroll
        for (int i = 0; i < 4; i++) {
            int l = tid * 4 + i;
            int row = l >> 4, col = l & 15;
            float v = 0.0f;
            if (m0 + row < M) {
                int off = (m0 + row) * KW + kb + k0 + col;
                v = Wa[off];
                if (WSUM) v += Wb[off];
            }
            pw[i] = v;
        }
    };
    auto loadX = [&](int k0) {
#pragma unroll
        for (int i = 0; i < 4; i++) {
            int l = tid + i * NTHR;
            float v = 0.0f;
            if (XMODE == 1) {
                int kr = l & 15, col = l >> 4;
                if (n0 + col < N) v = gx.X[(n0 + col) * gx.KX + kb + k0 + kr];
            } else if (XMODE == 0) {
                int kr = l >> 6, col = l & 63;
                if (n0 + col < N) v = gx.X[(kb + k0 + kr) * N + n0 + col];
            } else {
                int kr = l >> 6, col = l & 63;
                if (n0 + col < N) {
                    int kk = k0 + kr;
                    v = gx.X[kk * N + n0 + col] + gx.Xb[kk * N + n0 + col] + gx.biasX[kk];
                }
            }
            px[i] = v;
        }
    };
    auto storeWX = [&]() {
#pragma unroll
        for (int i = 0; i < 4; i++) {
            int l = tid * 4 + i;
            sm.gemm.Ws[l & 15][l >> 4] = pw[i];
        }
#pragma unroll
        for (int i = 0; i < 4; i++) {
            int l = tid + i * NTHR;
            if (XMODE == 1) sm.gemm.Xs[l & 15][l >> 4] = px[i];
            else            sm.gemm.Xs[l >> 6][l & 63] = px[i];
        }
    };

    loadW(0); loadX(0);
    for (int k0 = 0; k0 < kLen; k0 += 16) {
        storeWX();
        __syncthreads();
        if (k0 + 16 < kLen) { loadW(k0 + 16); loadX(k0 + 16); }
#pragma unroll
        for (int kk = 0; kk < 16; kk++) {
            float4 a4 = *(const float4*)&sm.gemm.Ws[kk][ty * 4];
            float4 b4 = *(const float4*)&sm.gemm.Xs[kk][tx * 4];
            float a[4] = {a4.x, a4.y, a4.z, a4.w};
            float bb[4] = {b4.x, b4.y, b4.z, b4.w};
#pragma unroll
            for (int i = 0; i < 4; i++)
#pragma unroll
                for (int j = 0; j < 4; j++)
                    acc[i][j] = fmaf(a[i], bb[j], acc[i][j]);
        }
        __syncthreads();
    }
#pragma unroll
    for (int i = 0; i < 4; i++) {
        int m = m0 + ty * 4 + i;
        if (m >= M) continue;
        float bv = (OUTMODE == 2) ? 0.0f : bias[m];
#pragma unroll
        for (int j = 0; j < 4; j++) {
            int n = n0 + tx * 4 + j;
            if (n >= N) continue;
            float v = acc[i][j] + bv;
            if (OUTMODE == 1) v = (v > 0.0f) ? v : 0.01f * v;
            Y[m * N + n] = v;
        }
    }
}

// --------------------------- megakernel -----------------------------------
__global__ void __launch_bounds__(NTHR, 2)
mega_kernel(const float* __restrict__ img, const float* __restrict__ cloud,
            const float* __restrict__ img_tar, const float* __restrict__ cloud_tar,
            const float* __restrict__ cur_feat, const float* __restrict__ tgt_feat,
            const float* __restrict__ Wc1, const float* __restrict__ bc1,
            const float* __restrict__ Wc2, const float* __restrict__ bc2,
            const float* __restrict__ Wp1, const float* __restrict__ bp1,
            const float* __restrict__ Wp2, const float* __restrict__ bp2,
            const float* __restrict__ Wfc1, const float* __restrict__ bfc1,
            const float* __restrict__ Wfc2, const float* __restrict__ bfc2,
            const float* __restrict__ Wfu2, const float* __restrict__ bfu2,
            const float* __restrict__ Wpn1, const float* __restrict__ bpn1,
            const float* __restrict__ Wpn2, const float* __restrict__ bpn2,
            const float* __restrict__ Wpn3, const float* __restrict__ bpn3,
            float* __restrict__ out) {
    __shared__ Smem sm;
    int b = blockIdx.x;
    int tid = threadIdx.x;
    GemmX gx = {};

    // ---- P0: KNN (0-93) || feat (94-157) || fold Weff (158-253) || misc
    if (b < 94) {
        int gw = b * 8 + (tid >> 5);
#pragma unroll
        for (int rep = 0; rep < 2; rep++) {
            int qid = gw + rep * 752;
            if (qid < 1500) {
                int task = (qid < 500) ? 0 : (qid < 1000 ? 1 : 2);
                int q = qid - task * 500;
                if (task == 0)      knn_warp<K12>(cloud,     cloud_tar, g_inds,      q);
                else if (task == 1) knn_warp<K12>(cloud_tar, cloud_tar, g_inds_self, q);
                else                knn_warp<KPP>(cloud_tar, cloud,     g_inds_pp,   q);
            }
        }
    } else if (b < 158) {
        dev_feat(b - 94, img, img_tar, cloud, cloud_tar,
                 Wc1, bc1, Wc2, bc2, Wp1, bp1, Wp2, bp2, sm);
    } else if (b < 254) {
        int u = b - 158;
        int half = u & 1, t = u >> 1;  // t: 0..47
        gx.X = Wpn1;
        gemm_tile<0, 2, 0>(Wpn2, nullptr, 256, half * 128, 128, gx, 160,
                           nullptr, g_Weffp + half * 1024 * 160, 1024,
                           (t / 3) * 64, (t % 3) * 64, sm);
    } else if (b == 254) {
        for (int m = tid; m < 1024; m += NTHR) {
            float a0 = 0.0f, a1 = 0.0f, a2 = 0.0f, a3 = 0.0f;
            const float* wr = Wpn2 + m * 256;
            for (int k = 0; k < 256; k += 4) {
                a0 = fmaf(wr[k], bpn1[k], a0);
                a1 = fmaf(wr[k + 1], bpn1[k + 1], a1);
                a2 = fmaf(wr[k + 2], bpn1[k + 2], a2);
                a3 = fmaf(wr[k + 3], bpn1[k + 3], a3);
            }
            g_beff[m] = bpn2[m] + ((a0 + a1) + (a2 + a3));
        }
    } else {
        if (tid < 64) { g_biasC[tid] = bfc2[tid]; g_biasC[64 + tid] = bfc1[tid]; }
        if (tid == 64) { g_sum[0] = 0.0f; g_sum[1] = 0.0f; }
    }
    gridbar(0);

    // ---- P1: softmax numerators + denominators (24 blocks)
    if (b < 24) {
        int task = b / 12, local = b % 12;
        const int* inds = task ? g_inds_self : g_inds;
        const float* refc = task ? cloud_tar : cloud;
        float* wout = task ? g_wcc : g_wct;
        float localsum = 0.0f;
        for (int j = local * NTHR + tid; j < N_PTS * K12; j += 12 * NTHR) {
            int q = j / K12;
            int r = inds[j];
            float dx = cloud_tar[q * 3 + 0] - refc[r * 3 + 0];
            float dy = cloud_tar[q * 3 + 1] - refc[r * 3 + 1];
            float dz = cloud_tar[q * 3 + 2] - refc[r * 3 + 2];
            float d = sqrtf(dx * dx + dy * dy + dz * dz + 1e-12f);
            float e = expf(-d);
            wout[j] = e;
            localsum += e;
        }
        sm.red.red[tid] = localsum;
        __syncthreads();
        for (int s = NTHR / 2; s > 0; s >>= 1) {
            if (tid < s) sm.red.red[tid] += sm.red.red[tid + s];
            __syncthreads();
        }
        if (tid == 0) atomicAdd(&g_sum[task], sm.red.red[0]);
    }
    gridbar(1);

    // ---- P2: pool1
    {
        float inv = 1.0f / g_sum[0];
        int sub = tid >> 7, ch = tid & 127;
        int n = b * 2 + sub;
        if (n < N_PTS) {
            float mi = -CUDART_INF_F, mp = -CUDART_INF_F;
#pragma unroll
            for (int k = 0; k < K12; k++) {
                int i = g_inds[n * K12 + k];
                float w = g_wct[n * K12 + k] * inv;
                mi = fmaxf(mi, g_itT[i * 128 + ch] * w);
                mp = fmaxf(mp, g_ctfT[i * 128 + ch] * w);
            }
            g_AT[n * 256 + ch] = g_icT[n * 128 + ch] - mi;
            g_BT[n * 256 + ch] = g_cfT[n * 128 + ch] - mp;
        }
    }
    gridbar(2);

    // ---- P3: pool2
    {
        float inv = 1.0f / g_sum[1];
        int sub = tid >> 7, ch = tid & 127;
        int n = b * 2 + sub;
        if (n < N_PTS) {
            float mspd = -CUDART_INF_F, msid = -CUDART_INF_F;
#pragma unroll
            for (int k = 0; k < K12; k++) {
                int i = g_inds_self[n * K12 + k];
                float w = g_wcc[n * K12 + k] * inv;
                mspd = fmaxf(mspd, g_BT[i * 256 + ch] * w);
                msid = fmaxf(msid, g_AT[i * 256 + ch] * w);
            }
            g_AT[n * 256 + 128 + ch] = mspd;
            g_BT[n * 256 + 128 + ch] = msid;
        }
    }
    gridbar(3);

    // ---- P4: fc2/fc1 split-K x2 -> partials (32 blocks)
    if (b < 32) {
        int half = b & 1, t = b >> 1;  // 0..15
        gx.KX = 256;
        if (t < 8) {
            gx.X = g_BT;
            gemm_tile<1, 2, 0>(Wfc2, nullptr, 256, half * 128, 128, gx, N_PTS,
                               nullptr, g_Cp + half * 128 * N_PTS, 64, 0, t * 64, sm);
        } else {
            gx.X = g_AT;
            gemm_tile<1, 2, 0>(Wfc1, nullptr, 256, half * 128, 128, gx, N_PTS,
                               nullptr, g_Cp + half * 128 * N_PTS + 64 * N_PTS, 64, 0,
                               (t - 8) * 64, sm);
        }
    }
    gridbar(4);

    // ---- P5: fuse2 with sum2 X loader (24 blocks)
    if (b < 24) {
        gx.X = g_Cp; gx.Xb = g_Cp + 128 * N_PTS; gx.biasX = g_biasC;
        gemm_tile<2, 0, 0>(Wfu2, nullptr, 128, 0, 128, gx, N_PTS,
                           bfu2, g_F, 160, (b >> 3) * 64, (b & 7) * 64, sm);
    }
    gridbar(5);

    // ---- P6: pn12 = lrelu(Weff @ F + beff) (128 blocks, W = sum of halves)
    if (b < 128) {
        gx.X = g_F;
        gemm_tile<0, 1, 1>(g_Weffp, g_Weffp + 1024 * 160, 160, 0, 160, gx, N_PTS,
                           g_beff, g_X2, 1024, (b >> 3) * 64, (b & 7) * 64, sm);
    }
    gridbar(6);

    // ---- P7: pn3 split-K x8 -> partials (192 blocks)
    if (b < 192) {
        int slab = b & 7, t = b >> 3;  // t: 0..23
        gx.X = g_X2;
        gemm_tile<0, 2, 0>(Wpn3, nullptr, 1024, slab * 128, 128, gx, N_PTS,
                           nullptr, g_part + slab * 160 * N_PTS, 160,
                           (t >> 3) * 64, (t & 7) * 64, sm);
    }
    gridbar(7);

    // ---- P8a: reduce partials, pre-multiply by tgt, point-major out
    for (int e = b * NTHR + tid; e < 160 * N_PTS; e += NBLK * NTHR) {
        int ch = e / N_PTS, n = e - ch * N_PTS;
        float v = bpn3[ch];
#pragma unroll
        for (int s = 0; s < 8; s++) v += g_part[s * 160 * N_PTS + e];
        g_X3T[n * 160 + ch] = tgt_feat[e] * v;
    }
    gridbar(8);

    // ---- P8b: final gather-mean
    if (tid < 160) {
        for (int n = b; n < N_PTS; n += NBLK) {
            float s = 0.0f;
#pragma unroll
            for (int k = 0; k < KPP; k++) {
                int i = g_inds_pp[n * KPP + k];
                s += g_X3T[i * 160 + tid];
            }
            out[tid * N_PTS + n] = cur_feat[tid * N_PTS + n] + 0.25f * s;
        }
    }
}

// --------------------------------------------------------------------------
extern "C" void kernel_launch(void* const* d_in, const int* in_sizes, int n_in,
                              void* d_out, int out_size) {
    mega_kernel<<<NBLK, NTHR>>>(
        (const float*)d_in[0],  (const float*)d_in[1],
        (const float*)d_in[2],  (const float*)d_in[3],
        (const float*)d_in[4],  (const float*)d_in[5],
        (const float*)d_in[6],  (const float*)d_in[7],
        (const float*)d_in[8],  (const float*)d_in[9],
        (const float*)d_in[10], (const float*)d_in[11],
        (const float*)d_in[12], (const float*)d_in[13],
        (const float*)d_in[14], (const float*)d_in[15],
        (const float*)d_in[16], (const float*)d_in[17],
        (const float*)d_in[18], (const float*)d_in[19],
        (const float*)d_in[20], (const float*)d_in[21],
        (const float*)d_in[22], (const float*)d_in[23],
        (const float*)d_in[24], (const float*)d_in[25],
        (float*)d_out);
}